// round 1
// baseline (speedup 1.0000x reference)
#include <cuda_runtime.h>
#include <math.h>

#define HH 192
#define WW 192
#define HW (192*192)

// ---- scratch (static device allocations; no cudaMalloc anywhere) ----
__device__ float g_h1[64 * HW];
__device__ float g_h2[64 * HW];
__device__ float g_out4[432 * HW];
__device__ float g_xT[HW * 128];   // x transposed to [h][w][c], c contiguous

// ============================================================================
// Direct 3x3 conv, pad=1, stride=1. Block: 256 threads -> 16(h) x 64(w) pixel
// tile, 8 output channels per block (blockIdx.z), 4 px per thread along w.
// Input channels processed in chunks of 8 through shared memory.
// ============================================================================
template<int CIN, bool RELU>
__global__ void __launch_bounds__(256) conv3x3_kernel(
    const float* __restrict__ in,   // [CIN][192][192]
    const float* __restrict__ wt,   // [COUT][CIN][3][3]
    const float* __restrict__ bs,   // [COUT]
    float* __restrict__ out)        // [COUT][192][192]
{
    __shared__ float s_in[8][18][68];   // 8 ci x (16+2) rows x (64+2) cols (padded)
    __shared__ float s_w[8][8][9];      // [oc][ci][k]

    const int tid = threadIdx.x;
    const int tx = tid & 15;            // 0..15 -> 4 px each along w
    const int ty = tid >> 4;            // 0..15 rows
    const int bw = blockIdx.x * 64;
    const int bh = blockIdx.y * 16;
    const int ocg0 = blockIdx.z * 8;

    float acc[8][4];
    #pragma unroll
    for (int o = 0; o < 8; o++)
        #pragma unroll
        for (int p = 0; p < 4; p++) acc[o][p] = 0.f;

    for (int ci0 = 0; ci0 < CIN; ci0 += 8) {
        __syncthreads();
        // cooperative input tile load (zero padding at borders)
        for (int li = tid; li < 8 * 18 * 66; li += 256) {
            int cc = li / (18 * 66);
            int r  = (li / 66) % 18;
            int c  = li % 66;
            int gy = bh - 1 + r;
            int gx = bw - 1 + c;
            float v = 0.f;
            if ((unsigned)gy < (unsigned)HH && (unsigned)gx < (unsigned)WW)
                v = in[(ci0 + cc) * HW + gy * WW + gx];
            s_in[cc][r][c] = v;
        }
        // cooperative weight load: 8 oc x 8 ci x 9
        for (int li = tid; li < 576; li += 256) {
            int oc = li / 72, r = li % 72, cc = r / 9, kk = r % 9;
            s_w[oc][cc][kk] = wt[((ocg0 + oc) * CIN + ci0 + cc) * 9 + kk];
        }
        __syncthreads();

        #pragma unroll
        for (int cc = 0; cc < 8; cc++) {
            float ir[3][6];
            #pragma unroll
            for (int dy = 0; dy < 3; dy++)
                #pragma unroll
                for (int dx = 0; dx < 6; dx++)
                    ir[dy][dx] = s_in[cc][ty + dy][tx * 4 + dx];
            #pragma unroll
            for (int oc = 0; oc < 8; oc++) {
                #pragma unroll
                for (int kh = 0; kh < 3; kh++)
                    #pragma unroll
                    for (int kw = 0; kw < 3; kw++) {
                        float wv = s_w[oc][cc][kh * 3 + kw];
                        #pragma unroll
                        for (int p = 0; p < 4; p++)
                            acc[oc][p] += ir[kh][kw + p] * wv;
                    }
            }
        }
    }

    #pragma unroll
    for (int oc = 0; oc < 8; oc++) {
        float bv = bs[ocg0 + oc];
        float t[4];
        #pragma unroll
        for (int p = 0; p < 4; p++) {
            float v = acc[oc][p] + bv;
            if (RELU) v = (v >= 0.f) ? v : 0.1f * v;
            t[p] = v;
        }
        float4 r4 = make_float4(t[0], t[1], t[2], t[3]);
        *(float4*)&out[(size_t)(ocg0 + oc) * HW + (bh + ty) * WW + bw + tx * 4] = r4;
    }
}

// ============================================================================
// Transpose x: [128][HW] (NCHW) -> [HW][128] (HWC). 32x32 smem tiles.
// grid: (HW/32 = 1152, 128/32 = 4), block 256.
// ============================================================================
__global__ void __launch_bounds__(256) transpose_kernel(
    const float* __restrict__ x, float* __restrict__ xT)
{
    __shared__ float s[32][33];
    int p0 = blockIdx.x * 32;
    int c0 = blockIdx.y * 32;
    int tx = threadIdx.x & 31;
    int ty = threadIdx.x >> 5;   // 0..7
    #pragma unroll
    for (int i = 0; i < 32; i += 8)
        s[ty + i][tx] = x[(size_t)(c0 + ty + i) * HW + p0 + tx];
    __syncthreads();
    #pragma unroll
    for (int i = 0; i < 32; i += 8)
        xT[(size_t)(p0 + ty + i) * 128 + c0 + tx] = s[tx][ty + i];
}

// ============================================================================
// Fused deformable conv. One block = 16 output pixels.
// Phase 1: build masked bilinear samples val[c*9+k][pix] in smem
//          (tanh/sigmoid applied inline on the conv4 output).
// Phase 2: 64(out-ch) x 16(px) GEMM over 1152, float4 smem reads.
// dynamic smem: 1152*16*4 = 73728 B
// ============================================================================
__global__ void __launch_bounds__(256) deform_kernel(
    const float* __restrict__ xT,    // [HW][128]
    const float* __restrict__ out4,  // [432][HW]
    const float* __restrict__ wt,    // [64][128][9]
    const float* __restrict__ bs,    // [64]
    float* __restrict__ out)         // [64][HW]
{
    extern __shared__ float val_s[]; // [1152][16]
    const int tid = threadIdx.x;
    const int pbase = blockIdx.x * 16;

    // ---- phase 1: sampling. 16 px * 16 groups * 9 taps = 2304 tasks ----
    for (int t = tid; t < 2304; t += 256) {
        int pix = t & 15;
        int gk  = t >> 4;          // 0..143
        int g   = gk / 9;
        int k   = gk % 9;
        int p   = pbase + pix;
        int ho  = p / WW;
        int wo  = p % WW;

        float oy = 5.f * tanhf(out4[(g * 18 + k * 2) * HW + p]);
        float ox = 5.f * tanhf(out4[(g * 18 + k * 2 + 1) * HW + p]);
        float mz = out4[(288 + g * 9 + k) * HW + p];
        float mv = 1.f / (1.f + expf(-mz));

        float py = (float)(ho - 1 + k / 3) + oy;
        float px = (float)(wo - 1 + k % 3) + ox;
        float y0 = floorf(py), x0 = floorf(px);
        float wy1 = py - y0, wx1 = px - x0;

        float v[8];
        #pragma unroll
        for (int c = 0; c < 8; c++) v[c] = 0.f;
        const int gc = g * 8;

        auto corner = [&](float iyf, float ixf, float wc) {
            if (iyf >= 0.f && iyf <= (float)(HH - 1) &&
                ixf >= 0.f && ixf <= (float)(WW - 1)) {
                int iy = (int)iyf, ix = (int)ixf;
                const float4* q = (const float4*)(xT + ((size_t)(iy * WW + ix) << 7) + gc);
                float4 a = q[0], b = q[1];
                v[0] += wc * a.x; v[1] += wc * a.y; v[2] += wc * a.z; v[3] += wc * a.w;
                v[4] += wc * b.x; v[5] += wc * b.y; v[6] += wc * b.z; v[7] += wc * b.w;
            }
        };
        corner(y0,       x0,       (1.f - wy1) * (1.f - wx1));
        corner(y0,       x0 + 1.f, (1.f - wy1) * wx1);
        corner(y0 + 1.f, x0,       wy1 * (1.f - wx1));
        corner(y0 + 1.f, x0 + 1.f, wy1 * wx1);

        #pragma unroll
        for (int c = 0; c < 8; c++)
            val_s[((gc + c) * 9 + k) * 16 + pix] = v[c] * mv;
    }
    __syncthreads();

    // ---- phase 2: out[o][pix] = sum_idx w[o][idx] * val[idx][pix] ----
    const int o  = tid & 63;
    const int ps = tid >> 6;    // 0..3 -> pixels ps*4 .. ps*4+3
    const float* wr = wt + o * 1152;
    const float4* vp = (const float4*)val_s;   // val_s[idx*16 + ps*4]
    float a0 = 0.f, a1 = 0.f, a2 = 0.f, a3 = 0.f;
    #pragma unroll 8
    for (int idx = 0; idx < 1152; idx++) {
        float wv = __ldg(wr + idx);
        float4 vv = vp[idx * 4 + ps];
        a0 += wv * vv.x; a1 += wv * vv.y; a2 += wv * vv.z; a3 += wv * vv.w;
    }
    float bv = bs[o];
    float4 r4 = make_float4(a0 + bv, a1 + bv, a2 + bv, a3 + bv);
    *(float4*)&out[(size_t)o * HW + pbase + ps * 4] = r4;
}

// ============================================================================
// launch
// ============================================================================
extern "C" void kernel_launch(void* const* d_in, const int* in_sizes, int n_in,
                              void* d_out, int out_size)
{
    const float* x      = (const float*)d_in[0];
    const float* cond   = (const float*)d_in[1];
    const float* weight = (const float*)d_in[2];
    const float* bias   = (const float*)d_in[3];
    const float* w1     = (const float*)d_in[4];
    const float* b1     = (const float*)d_in[5];
    const float* w2     = (const float*)d_in[6];
    const float* b2     = (const float*)d_in[7];
    const float* w3     = (const float*)d_in[8];
    const float* b3     = (const float*)d_in[9];
    const float* w4     = (const float*)d_in[10];
    const float* b4     = (const float*)d_in[11];
    float* out = (float*)d_out;

    float *h1, *h2, *o4, *xT;
    cudaGetSymbolAddress((void**)&h1, g_h1);
    cudaGetSymbolAddress((void**)&h2, g_h2);
    cudaGetSymbolAddress((void**)&o4, g_out4);
    cudaGetSymbolAddress((void**)&xT, g_xT);

    dim3 cgrid(3, 12, 8);
    conv3x3_kernel<192, true ><<<cgrid, 256>>>(cond, w1, b1, h1);
    conv3x3_kernel< 64, true ><<<cgrid, 256>>>(h1,   w2, b2, h2);
    conv3x3_kernel< 64, true ><<<cgrid, 256>>>(h2,   w3, b3, h1);
    dim3 cgrid4(3, 12, 54);
    conv3x3_kernel< 64, false><<<cgrid4, 256>>>(h1,  w4, b4, o4);

    transpose_kernel<<<dim3(1152, 4), 256>>>(x, xT);

    static const size_t smem = 1152 * 16 * sizeof(float);
    cudaFuncSetAttribute(deform_kernel,
                         cudaFuncAttributeMaxDynamicSharedMemorySize, (int)smem);
    deform_kernel<<<2304, 256, smem>>>(xT, o4, weight, bias, out);
}

// round 4
// speedup vs baseline: 2.1692x; 2.1692x over previous
#include <cuda_runtime.h>
#include <math.h>

#define HH 192
#define WW 192
#define HW (192*192)

typedef unsigned long long u64;

// ---- packed fp32x2 helpers (sm_103a FFMA2 path, PTX-only) ----
__device__ __forceinline__ u64 pack2(float a, float b) {
    u64 r; asm("mov.b64 %0, {%1, %2};" : "=l"(r) : "f"(a), "f"(b)); return r;
}
__device__ __forceinline__ float2 unpack2(u64 v) {
    float2 f; asm("mov.b64 {%0, %1}, %2;" : "=f"(f.x), "=f"(f.y) : "l"(v)); return f;
}
__device__ __forceinline__ u64 fma2(u64 a, u64 b, u64 c) {
    u64 d; asm("fma.rn.f32x2 %0, %1, %2, %3;" : "=l"(d) : "l"(a), "l"(b), "l"(c)); return d;
}
__device__ __forceinline__ u64 mul2(u64 a, u64 b) {
    u64 d; asm("mul.rn.f32x2 %0, %1, %2;" : "=l"(d) : "l"(a), "l"(b)); return d;
}

// ---- scratch (static device allocations; no cudaMalloc anywhere) ----
__device__ float g_h1[64 * HW];
__device__ float g_h2[64 * HW];
__device__ float g_out4[432 * HW];
__device__ float g_xT[HW * 128];   // x transposed to [h][w][c], c contiguous

// ============================================================================
// Direct 3x3 conv via FFMA2. Block: 256 thr -> 16(h) x 64(w) px tile,
// OCG output channels per block (blockIdx.z). 4 px/thread as 2 f32x2 pairs.
// ============================================================================
template<int CIN, int OCG, bool RELU>
__global__ void __launch_bounds__(256) conv3x3_kernel(
    const float* __restrict__ in,   // [CIN][192][192]
    const float* __restrict__ wt,   // [COUT][CIN][3][3]
    const float* __restrict__ bs,   // [COUT]
    float* __restrict__ out)        // [COUT][192][192]
{
    __shared__ float s_in[8][18][68];   // (16+2) rows x (64+2) cols
    __shared__ u64   s_w[OCG][8][9];    // duplicated weight pairs (w,w)

    const int tid  = threadIdx.x;
    const int tx   = tid & 15;          // 4 px each along w
    const int ty   = tid >> 4;          // row 0..15
    const int lane = tid & 31;
    const int wid  = tid >> 5;
    const int bw   = blockIdx.x * 64;
    const int bh   = blockIdx.y * 16;
    const int ocg0 = blockIdx.z * OCG;

    u64 acc2[OCG][2];
    #pragma unroll
    for (int o = 0; o < OCG; o++) { acc2[o][0] = 0ull; acc2[o][1] = 0ull; }

    for (int ci0 = 0; ci0 < CIN; ci0 += 8) {
        __syncthreads();
        // weights: OCG*8*9 entries, duplicated pairs
        for (int li = tid; li < OCG * 72; li += 256) {
            int oc = li / 72, r = li - oc * 72;
            int cc = r / 9,  kk = r - cc * 9;
            float w = wt[((ocg0 + oc) * CIN + ci0 + cc) * 9 + kk];
            s_w[oc][cc][kk] = pack2(w, w);
        }
        // input tile: warp per row
        for (int row = wid; row < 144; row += 8) {
            int cc = row / 18;
            int r  = row - cc * 18;
            int gy = bh - 1 + r;
            bool yok = (unsigned)gy < (unsigned)HH;
            const float* src = in + (size_t)(ci0 + cc) * HW + gy * WW + (bw - 1);
            int c0 = lane, c1 = lane + 32, c2 = lane + 64;
            float v0 = 0.f, v1 = 0.f;
            if (yok) {
                int g0 = bw - 1 + c0; if ((unsigned)g0 < (unsigned)WW) v0 = src[c0];
                int g1 = bw - 1 + c1; if ((unsigned)g1 < (unsigned)WW) v1 = src[c1];
            }
            s_in[cc][r][c0] = v0;
            s_in[cc][r][c1] = v1;
            if (c2 < 66) {
                float v2 = 0.f;
                if (yok) { int g2 = bw - 1 + c2; if ((unsigned)g2 < (unsigned)WW) v2 = src[c2]; }
                s_in[cc][r][c2] = v2;
            }
        }
        __syncthreads();

        #pragma unroll
        for (int cc = 0; cc < 8; cc++) {
            u64 ir2[3][5];
            #pragma unroll
            for (int dy = 0; dy < 3; dy++) {
                const float* rp = &s_in[cc][ty + dy][tx * 4];
                float4 a = *(const float4*)rp;
                float2 b = *(const float2*)(rp + 4);
                ir2[dy][0] = pack2(a.x, a.y);
                ir2[dy][1] = pack2(a.y, a.z);
                ir2[dy][2] = pack2(a.z, a.w);
                ir2[dy][3] = pack2(a.w, b.x);
                ir2[dy][4] = pack2(b.x, b.y);
            }
            #pragma unroll
            for (int oc = 0; oc < OCG; oc++) {
                #pragma unroll
                for (int kh = 0; kh < 3; kh++) {
                    #pragma unroll
                    for (int kw = 0; kw < 3; kw++) {
                        u64 w2 = s_w[oc][cc][kh * 3 + kw];
                        acc2[oc][0] = fma2(w2, ir2[kh][kw],     acc2[oc][0]);
                        acc2[oc][1] = fma2(w2, ir2[kh][kw + 2], acc2[oc][1]);
                    }
                }
            }
        }
    }

    #pragma unroll
    for (int oc = 0; oc < OCG; oc++) {
        float bv = bs[ocg0 + oc];
        float2 lo = unpack2(acc2[oc][0]);
        float2 hi = unpack2(acc2[oc][1]);
        float t0 = lo.x + bv, t1 = lo.y + bv, t2 = hi.x + bv, t3 = hi.y + bv;
        if (RELU) {
            t0 = (t0 >= 0.f) ? t0 : 0.1f * t0;
            t1 = (t1 >= 0.f) ? t1 : 0.1f * t1;
            t2 = (t2 >= 0.f) ? t2 : 0.1f * t2;
            t3 = (t3 >= 0.f) ? t3 : 0.1f * t3;
        }
        *(float4*)&out[(size_t)(ocg0 + oc) * HW + (bh + ty) * WW + bw + tx * 4] =
            make_float4(t0, t1, t2, t3);
    }
}

// ============================================================================
// Transpose x: [128][HW] -> [HW][128]. 32x32 smem tiles.
// ============================================================================
__global__ void __launch_bounds__(256) transpose_kernel(
    const float* __restrict__ x, float* __restrict__ xT)
{
    __shared__ float s[32][33];
    int p0 = blockIdx.x * 32;
    int c0 = blockIdx.y * 32;
    int tx = threadIdx.x & 31;
    int ty = threadIdx.x >> 5;
    #pragma unroll
    for (int i = 0; i < 32; i += 8)
        s[ty + i][tx] = x[(size_t)(c0 + ty + i) * HW + p0 + tx];
    __syncthreads();
    #pragma unroll
    for (int i = 0; i < 32; i += 8)
        xT[(size_t)(p0 + ty + i) * 128 + c0 + tx] = s[tx][ty + i];
}

// ============================================================================
// Fused deformable conv. Block = 32 output pixels, 256 threads.
// Loop over 16 deform groups:
//   stage weights [64][72] (coalesced) + build masked bilinear val [72][32]
//   then FFMA2 GEMM: each thread does 2 oc x 4 px.
// smem = 9216 (val) + 18688 (weights, stride 73) ~= 28KB
// ============================================================================
#define DPX 32
__global__ void __launch_bounds__(256) deform_kernel(
    const float* __restrict__ xT,    // [HW][128]
    const float* __restrict__ out4,  // [432][HW]
    const float* __restrict__ wt,    // [64][128][9]
    const float* __restrict__ bs,    // [64]
    float* __restrict__ out)         // [64][HW]
{
    __shared__ float val_s[72 * DPX];
    __shared__ float w_s[64 * 73];

    const int tid = threadIdx.x;
    const int pbase = blockIdx.x * DPX;
    const int o  = tid & 31;     // oc pair (o, o+32)
    const int ps = tid >> 5;     // 0..7 -> pixels ps*4..ps*4+3

    u64 acc[2][2];
    acc[0][0] = acc[0][1] = acc[1][0] = acc[1][1] = 0ull;

    for (int g = 0; g < 16; g++) {
        __syncthreads();
        // stage weights for this group: w[oo][g*72 + j]
        for (int li = tid; li < 4608; li += 256) {
            int oo = li / 72;
            int j  = li - oo * 72;
            w_s[oo * 73 + j] = wt[oo * 1152 + g * 72 + j];
        }
        // build val tile: 9 taps x 32 px
        for (int t = tid; t < 9 * DPX; t += 256) {
            int pix = t & (DPX - 1);
            int k   = t >> 5;
            int p   = pbase + pix;
            int ho  = p / WW;
            int wo  = p - ho * WW;

            float offy = 5.f * tanhf(out4[(g * 18 + k * 2)     * HW + p]);
            float offx = 5.f * tanhf(out4[(g * 18 + k * 2 + 1) * HW + p]);
            float mz   = out4[(288 + g * 9 + k) * HW + p];
            float mv   = 1.f / (1.f + expf(-mz));

            float py = (float)(ho - 1 + k / 3) + offy;
            float px = (float)(wo - 1 + k % 3) + offx;
            float y0 = floorf(py), x0 = floorf(px);
            float wy1 = py - y0, wx1 = px - x0;

            u64 v2[4] = {0ull, 0ull, 0ull, 0ull};

            auto corner = [&](float yf, float xf, float wc) {
                if (yf >= 0.f && yf <= (float)(HH - 1) &&
                    xf >= 0.f && xf <= (float)(WW - 1)) {
                    int iy = (int)yf, ix = (int)xf;
                    const ulonglong2* q =
                        (const ulonglong2*)(xT + ((size_t)(iy * WW + ix) << 7) + (g << 3));
                    ulonglong2 q0 = q[0], q1 = q[1];
                    u64 wc2 = pack2(wc, wc);
                    v2[0] = fma2(wc2, q0.x, v2[0]);
                    v2[1] = fma2(wc2, q0.y, v2[1]);
                    v2[2] = fma2(wc2, q1.x, v2[2]);
                    v2[3] = fma2(wc2, q1.y, v2[3]);
                }
            };
            corner(y0,       x0,       (1.f - wy1) * (1.f - wx1));
            corner(y0,       x0 + 1.f, (1.f - wy1) * wx1);
            corner(y0 + 1.f, x0,       wy1 * (1.f - wx1));
            corner(y0 + 1.f, x0 + 1.f, wy1 * wx1);

            u64 m2 = pack2(mv, mv);
            #pragma unroll
            for (int c2 = 0; c2 < 4; c2++) {
                float2 ff = unpack2(mul2(v2[c2], m2));
                val_s[((c2 * 2)     * 9 + k) * DPX + pix] = ff.x;
                val_s[((c2 * 2 + 1) * 9 + k) * DPX + pix] = ff.y;
            }
        }
        __syncthreads();

        // GEMM: acc[o][px] += w[o][j] * val[j][px]
        const float* wr0 = &w_s[o * 73];
        const float* wr1 = &w_s[(o + 32) * 73];
        const float* vb  = &val_s[ps * 4];
        #pragma unroll 4
        for (int j = 0; j < 72; j++) {
            float w0 = wr0[j], w1 = wr1[j];
            u64 w02 = pack2(w0, w0);
            u64 w12 = pack2(w1, w1);
            const u64* vp = (const u64*)(vb + j * DPX);   // broadcast across warp
            u64 v0 = vp[0], v1 = vp[1];
            acc[0][0] = fma2(w02, v0, acc[0][0]);
            acc[0][1] = fma2(w02, v1, acc[0][1]);
            acc[1][0] = fma2(w12, v0, acc[1][0]);
            acc[1][1] = fma2(w12, v1, acc[1][1]);
        }
    }

    float bv0 = bs[o], bv1 = bs[o + 32];
    float2 a0 = unpack2(acc[0][0]), a1 = unpack2(acc[0][1]);
    float2 b0 = unpack2(acc[1][0]), b1 = unpack2(acc[1][1]);
    *(float4*)&out[(size_t)o        * HW + pbase + ps * 4] =
        make_float4(a0.x + bv0, a0.y + bv0, a1.x + bv0, a1.y + bv0);
    *(float4*)&out[(size_t)(o + 32) * HW + pbase + ps * 4] =
        make_float4(b0.x + bv1, b0.y + bv1, b1.x + bv1, b1.y + bv1);
}

// ============================================================================
// launch
// ============================================================================
extern "C" void kernel_launch(void* const* d_in, const int* in_sizes, int n_in,
                              void* d_out, int out_size)
{
    const float* x      = (const float*)d_in[0];
    const float* cond   = (const float*)d_in[1];
    const float* weight = (const float*)d_in[2];
    const float* bias   = (const float*)d_in[3];
    const float* w1     = (const float*)d_in[4];
    const float* b1     = (const float*)d_in[5];
    const float* w2     = (const float*)d_in[6];
    const float* b2     = (const float*)d_in[7];
    const float* w3     = (const float*)d_in[8];
    const float* b3     = (const float*)d_in[9];
    const float* w4     = (const float*)d_in[10];
    const float* b4     = (const float*)d_in[11];
    float* out = (float*)d_out;

    float *h1, *h2, *o4, *xT;
    cudaGetSymbolAddress((void**)&h1, g_h1);
    cudaGetSymbolAddress((void**)&h2, g_h2);
    cudaGetSymbolAddress((void**)&o4, g_out4);
    cudaGetSymbolAddress((void**)&xT, g_xT);

    dim3 cgrid(3, 12, 8);
    conv3x3_kernel<192, 8, true ><<<cgrid, 256>>>(cond, w1, b1, h1);
    conv3x3_kernel< 64, 8, true ><<<cgrid, 256>>>(h1,   w2, b2, h2);
    conv3x3_kernel< 64, 8, true ><<<cgrid, 256>>>(h2,   w3, b3, h1);
    dim3 cgrid4(3, 12, 54);
    conv3x3_kernel< 64, 8, false><<<cgrid4, 256>>>(h1,  w4, b4, o4);

    transpose_kernel<<<dim3(1152, 4), 256>>>(x, xT);

    deform_kernel<<<HW / DPX, 256>>>(xT, o4, weight, bias, out);
}

// round 5
// speedup vs baseline: 2.4660x; 1.1368x over previous
#include <cuda_runtime.h>
#include <math.h>

#define HH 192
#define WW 192
#define HW (192*192)

typedef unsigned long long u64;

// ---- packed fp32x2 helpers (sm_103a FFMA2 path, PTX-only) ----
__device__ __forceinline__ u64 pack2(float a, float b) {
    u64 r; asm("mov.b64 %0, {%1, %2};" : "=l"(r) : "f"(a), "f"(b)); return r;
}
__device__ __forceinline__ float2 unpack2(u64 v) {
    float2 f; asm("mov.b64 {%0, %1}, %2;" : "=f"(f.x), "=f"(f.y) : "l"(v)); return f;
}
__device__ __forceinline__ u64 fma2(u64 a, u64 b, u64 c) {
    u64 d; asm("fma.rn.f32x2 %0, %1, %2, %3;" : "=l"(d) : "l"(a), "l"(b), "l"(c)); return d;
}
__device__ __forceinline__ u64 mul2(u64 a, u64 b) {
    u64 d; asm("mul.rn.f32x2 %0, %1, %2;" : "=l"(d) : "l"(a), "l"(b)); return d;
}

// ---- scratch (static device allocations; no cudaMalloc anywhere) ----
__device__ float g_h1[64 * HW];
__device__ float g_h2[64 * HW];
__device__ float g_out4[432 * HW];
__device__ float g_xT[HW * 128];   // x transposed to [h][w][c], c contiguous

// ============================================================================
// Direct 3x3 conv via FFMA2, packed over OUTPUT-CHANNEL pairs (oc, oc+4).
// One weight LDS.64 feeds 4 FFMA2 (4 pixels). Block: 256 thr -> 16x64 px tile,
// 8 output channels (4 pairs) per blockIdx.z. 4 px/thread.
// ============================================================================
template<int CIN, bool RELU>
__global__ void __launch_bounds__(256, 2) conv3x3_kernel(
    const float* __restrict__ in,   // [CIN][192][192]
    const float* __restrict__ wt,   // [COUT][CIN][3][3]
    const float* __restrict__ bs,   // [COUT]
    float* __restrict__ out)        // [COUT][192][192]
{
    __shared__ float s_in[8][18][68];   // (16+2) rows x (64+2) cols
    __shared__ u64   s_w[4][8][9];      // pack2(w[oc], w[oc+4])

    const int tid  = threadIdx.x;
    const int tx   = tid & 15;          // 4 px each along w
    const int ty   = tid >> 4;          // row 0..15
    const int lane = tid & 31;
    const int wid  = tid >> 5;
    const int bw   = blockIdx.x * 64;
    const int bh   = blockIdx.y * 16;
    const int ocg0 = blockIdx.z * 8;

    u64 acc[4][4];                      // [oc-pair][px] = (oc, oc+4)
    #pragma unroll
    for (int p = 0; p < 4; p++)
        #pragma unroll
        for (int q = 0; q < 4; q++) acc[p][q] = 0ull;

    for (int ci0 = 0; ci0 < CIN; ci0 += 8) {
        __syncthreads();
        // weights: 4 pairs x 8 ci x 9 taps
        for (int li = tid; li < 288; li += 256) {
            int pr = li / 72, r = li - pr * 72;
            int cc = r / 9,  kk = r - cc * 9;
            float wa = wt[((ocg0 + pr)     * CIN + ci0 + cc) * 9 + kk];
            float wb = wt[((ocg0 + pr + 4) * CIN + ci0 + cc) * 9 + kk];
            s_w[pr][cc][kk] = pack2(wa, wb);
        }
        // input tile: warp per row
        for (int row = wid; row < 144; row += 8) {
            int cc = row / 18;
            int r  = row - cc * 18;
            int gy = bh - 1 + r;
            bool yok = (unsigned)gy < (unsigned)HH;
            const float* src = in + (size_t)(ci0 + cc) * HW + gy * WW + (bw - 1);
            int c0 = lane, c1 = lane + 32, c2 = lane + 64;
            float v0 = 0.f, v1 = 0.f;
            if (yok) {
                int g0 = bw - 1 + c0; if ((unsigned)g0 < (unsigned)WW) v0 = src[c0];
                int g1 = bw - 1 + c1; if ((unsigned)g1 < (unsigned)WW) v1 = src[c1];
            }
            s_in[cc][r][c0] = v0;
            s_in[cc][r][c1] = v1;
            if (c2 < 66) {
                float v2 = 0.f;
                if (yok) { int g2 = bw - 1 + c2; if ((unsigned)g2 < (unsigned)WW) v2 = src[c2]; }
                s_in[cc][r][c2] = v2;
            }
        }
        __syncthreads();

        #pragma unroll
        for (int cc = 0; cc < 8; cc++) {
            #pragma unroll
            for (int kh = 0; kh < 3; kh++) {
                const float* rp = &s_in[cc][ty + kh][tx * 4];
                float4 a = *(const float4*)rp;
                float2 b = *(const float2*)(rp + 4);
                u64 d[6];
                d[0] = pack2(a.x, a.x);
                d[1] = pack2(a.y, a.y);
                d[2] = pack2(a.z, a.z);
                d[3] = pack2(a.w, a.w);
                d[4] = pack2(b.x, b.x);
                d[5] = pack2(b.y, b.y);
                #pragma unroll
                for (int pr = 0; pr < 4; pr++) {
                    u64 w0 = s_w[pr][cc][kh * 3 + 0];
                    u64 w1 = s_w[pr][cc][kh * 3 + 1];
                    u64 w2 = s_w[pr][cc][kh * 3 + 2];
                    #pragma unroll
                    for (int px = 0; px < 4; px++) {
                        acc[pr][px] = fma2(w0, d[px],     acc[pr][px]);
                        acc[pr][px] = fma2(w1, d[px + 1], acc[pr][px]);
                        acc[pr][px] = fma2(w2, d[px + 2], acc[pr][px]);
                    }
                }
            }
        }
    }

    const size_t obase = (size_t)(bh + ty) * WW + bw + tx * 4;
    #pragma unroll
    for (int pr = 0; pr < 4; pr++) {
        float bva = bs[ocg0 + pr];
        float bvb = bs[ocg0 + pr + 4];
        float ra[4], rb[4];
        #pragma unroll
        for (int px = 0; px < 4; px++) {
            float2 f = unpack2(acc[pr][px]);
            float va = f.x + bva;
            float vb = f.y + bvb;
            if (RELU) {
                va = (va >= 0.f) ? va : 0.1f * va;
                vb = (vb >= 0.f) ? vb : 0.1f * vb;
            }
            ra[px] = va; rb[px] = vb;
        }
        *(float4*)&out[(size_t)(ocg0 + pr)     * HW + obase] =
            make_float4(ra[0], ra[1], ra[2], ra[3]);
        *(float4*)&out[(size_t)(ocg0 + pr + 4) * HW + obase] =
            make_float4(rb[0], rb[1], rb[2], rb[3]);
    }
}

// ============================================================================
// Transpose x: [128][HW] -> [HW][128]. 32x32 smem tiles.
// ============================================================================
__global__ void __launch_bounds__(256) transpose_kernel(
    const float* __restrict__ x, float* __restrict__ xT)
{
    __shared__ float s[32][33];
    int p0 = blockIdx.x * 32;
    int c0 = blockIdx.y * 32;
    int tx = threadIdx.x & 31;
    int ty = threadIdx.x >> 5;
    #pragma unroll
    for (int i = 0; i < 32; i += 8)
        s[ty + i][tx] = x[(size_t)(c0 + ty + i) * HW + p0 + tx];
    __syncthreads();
    #pragma unroll
    for (int i = 0; i < 32; i += 8)
        xT[(size_t)(p0 + ty + i) * 128 + c0 + tx] = s[tx][ty + i];
}

// ============================================================================
// Fused deformable conv (unchanged from R4 — it went ~2.6ms -> ~400us).
// ============================================================================
#define DPX 32
__global__ void __launch_bounds__(256) deform_kernel(
    const float* __restrict__ xT,    // [HW][128]
    const float* __restrict__ out4,  // [432][HW]
    const float* __restrict__ wt,    // [64][128][9]
    const float* __restrict__ bs,    // [64]
    float* __restrict__ out)         // [64][HW]
{
    __shared__ float val_s[72 * DPX];
    __shared__ float w_s[64 * 73];

    const int tid = threadIdx.x;
    const int pbase = blockIdx.x * DPX;
    const int o  = tid & 31;     // oc pair (o, o+32)
    const int ps = tid >> 5;     // 0..7 -> pixels ps*4..ps*4+3

    u64 acc[2][2];
    acc[0][0] = acc[0][1] = acc[1][0] = acc[1][1] = 0ull;

    for (int g = 0; g < 16; g++) {
        __syncthreads();
        for (int li = tid; li < 4608; li += 256) {
            int oo = li / 72;
            int j  = li - oo * 72;
            w_s[oo * 73 + j] = wt[oo * 1152 + g * 72 + j];
        }
        for (int t = tid; t < 9 * DPX; t += 256) {
            int pix = t & (DPX - 1);
            int k   = t >> 5;
            int p   = pbase + pix;
            int ho  = p / WW;
            int wo  = p - ho * WW;

            float offy = 5.f * tanhf(out4[(g * 18 + k * 2)     * HW + p]);
            float offx = 5.f * tanhf(out4[(g * 18 + k * 2 + 1) * HW + p]);
            float mz   = out4[(288 + g * 9 + k) * HW + p];
            float mv   = 1.f / (1.f + expf(-mz));

            float py = (float)(ho - 1 + k / 3) + offy;
            float px = (float)(wo - 1 + k % 3) + offx;
            float y0 = floorf(py), x0 = floorf(px);
            float wy1 = py - y0, wx1 = px - x0;

            u64 v2[4] = {0ull, 0ull, 0ull, 0ull};

            auto corner = [&](float yf, float xf, float wc) {
                if (yf >= 0.f && yf <= (float)(HH - 1) &&
                    xf >= 0.f && xf <= (float)(WW - 1)) {
                    int iy = (int)yf, ix = (int)xf;
                    const ulonglong2* q =
                        (const ulonglong2*)(xT + ((size_t)(iy * WW + ix) << 7) + (g << 3));
                    ulonglong2 q0 = q[0], q1 = q[1];
                    u64 wc2 = pack2(wc, wc);
                    v2[0] = fma2(wc2, q0.x, v2[0]);
                    v2[1] = fma2(wc2, q0.y, v2[1]);
                    v2[2] = fma2(wc2, q1.x, v2[2]);
                    v2[3] = fma2(wc2, q1.y, v2[3]);
                }
            };
            corner(y0,       x0,       (1.f - wy1) * (1.f - wx1));
            corner(y0,       x0 + 1.f, (1.f - wy1) * wx1);
            corner(y0 + 1.f, x0,       wy1 * (1.f - wx1));
            corner(y0 + 1.f, x0 + 1.f, wy1 * wx1);

            u64 m2 = pack2(mv, mv);
            #pragma unroll
            for (int c2 = 0; c2 < 4; c2++) {
                float2 ff = unpack2(mul2(v2[c2], m2));
                val_s[((c2 * 2)     * 9 + k) * DPX + pix] = ff.x;
                val_s[((c2 * 2 + 1) * 9 + k) * DPX + pix] = ff.y;
            }
        }
        __syncthreads();

        const float* wr0 = &w_s[o * 73];
        const float* wr1 = &w_s[(o + 32) * 73];
        const float* vb  = &val_s[ps * 4];
        #pragma unroll 4
        for (int j = 0; j < 72; j++) {
            float w0 = wr0[j], w1 = wr1[j];
            u64 w02 = pack2(w0, w0);
            u64 w12 = pack2(w1, w1);
            const u64* vp = (const u64*)(vb + j * DPX);
            u64 v0 = vp[0], v1 = vp[1];
            acc[0][0] = fma2(w02, v0, acc[0][0]);
            acc[0][1] = fma2(w02, v1, acc[0][1]);
            acc[1][0] = fma2(w12, v0, acc[1][0]);
            acc[1][1] = fma2(w12, v1, acc[1][1]);
        }
    }

    float bv0 = bs[o], bv1 = bs[o + 32];
    float2 a0 = unpack2(acc[0][0]), a1 = unpack2(acc[0][1]);
    float2 b0 = unpack2(acc[1][0]), b1 = unpack2(acc[1][1]);
    *(float4*)&out[(size_t)o        * HW + pbase + ps * 4] =
        make_float4(a0.x + bv0, a0.y + bv0, a1.x + bv0, a1.y + bv0);
    *(float4*)&out[(size_t)(o + 32) * HW + pbase + ps * 4] =
        make_float4(b0.x + bv1, b0.y + bv1, b1.x + bv1, b1.y + bv1);
}

// ============================================================================
// launch
// ============================================================================
extern "C" void kernel_launch(void* const* d_in, const int* in_sizes, int n_in,
                              void* d_out, int out_size)
{
    const float* x      = (const float*)d_in[0];
    const float* cond   = (const float*)d_in[1];
    const float* weight = (const float*)d_in[2];
    const float* bias   = (const float*)d_in[3];
    const float* w1     = (const float*)d_in[4];
    const float* b1     = (const float*)d_in[5];
    const float* w2     = (const float*)d_in[6];
    const float* b2     = (const float*)d_in[7];
    const float* w3     = (const float*)d_in[8];
    const float* b3     = (const float*)d_in[9];
    const float* w4     = (const float*)d_in[10];
    const float* b4     = (const float*)d_in[11];
    float* out = (float*)d_out;

    float *h1, *h2, *o4, *xT;
    cudaGetSymbolAddress((void**)&h1, g_h1);
    cudaGetSymbolAddress((void**)&h2, g_h2);
    cudaGetSymbolAddress((void**)&o4, g_out4);
    cudaGetSymbolAddress((void**)&xT, g_xT);

    dim3 cgrid(3, 12, 8);
    conv3x3_kernel<192, true ><<<cgrid, 256>>>(cond, w1, b1, h1);
    conv3x3_kernel< 64, true ><<<cgrid, 256>>>(h1,   w2, b2, h2);
    conv3x3_kernel< 64, true ><<<cgrid, 256>>>(h2,   w3, b3, h1);
    dim3 cgrid4(3, 12, 54);
    conv3x3_kernel< 64, false><<<cgrid4, 256>>>(h1,  w4, b4, o4);

    transpose_kernel<<<dim3(1152, 4), 256>>>(x, xT);

    deform_kernel<<<HW / DPX, 256>>>(xT, o4, weight, bias, out);
}

// round 6
// speedup vs baseline: 3.4843x; 1.4130x over previous
#include <cuda_runtime.h>
#include <math.h>

#define HH 192
#define WW 192
#define HW (192*192)

typedef unsigned long long u64;

// ---- packed fp32x2 helpers ----
__device__ __forceinline__ u64 pack2(float a, float b) {
    u64 r; asm("mov.b64 %0, {%1, %2};" : "=l"(r) : "f"(a), "f"(b)); return r;
}
__device__ __forceinline__ float2 unpack2(u64 v) {
    float2 f; asm("mov.b64 {%0, %1}, %2;" : "=f"(f.x), "=f"(f.y) : "l"(v)); return f;
}
__device__ __forceinline__ u64 fma2(u64 a, u64 b, u64 c) {
    u64 d; asm("fma.rn.f32x2 %0, %1, %2, %3;" : "=l"(d) : "l"(a), "l"(b), "l"(c)); return d;
}
__device__ __forceinline__ u64 mul2(u64 a, u64 b) {
    u64 d; asm("mul.rn.f32x2 %0, %1, %2;" : "=l"(d) : "l"(a), "l"(b)); return d;
}

// ---- cp.async helpers ----
__device__ __forceinline__ void cp4(unsigned daddr, const float* src, bool valid) {
    asm volatile("cp.async.ca.shared.global [%0], [%1], 4, %2;"
                 :: "r"(daddr), "l"(src), "r"(valid ? 4u : 0u));
}
__device__ __forceinline__ void cp16(unsigned daddr, const void* src) {
    asm volatile("cp.async.cg.shared.global [%0], [%1], 16;" :: "r"(daddr), "l"(src));
}
__device__ __forceinline__ void cp_commit() {
    asm volatile("cp.async.commit_group;");
}
template<int N> __device__ __forceinline__ void cp_wait() {
    asm volatile("cp.async.wait_group %0;" :: "n"(N));
}

// ---- scratch ----
__device__ float g_h1[64 * HW];
__device__ float g_h2[64 * HW];
__device__ float g_out4[432 * HW];
__device__ float g_xT[HW * 128];
__device__ u64 g_pw1[8  * 192 * 36];   // packed weights: [ocg][ci][pr][9]
__device__ u64 g_pw2[8  *  64 * 36];
__device__ u64 g_pw3[8  *  64 * 36];
__device__ u64 g_pw4[54 *  64 * 36];

// ============================================================================
// Weight prepack: dst[((ocg*CIN+ci)*4+pr)*9+kk] = (w[ocg*8+pr], w[ocg*8+pr+4])
// ============================================================================
__global__ void prepack_kernel(const float* __restrict__ wt, int CIN, int nOcg,
                               u64* __restrict__ dst)
{
    int i = blockIdx.x * 256 + threadIdx.x;
    int total = nOcg * CIN * 36;
    if (i >= total) return;
    int kk = i % 9; int t = i / 9;
    int pr = t % 4; t /= 4;
    int ci = t % CIN; int ocg = t / CIN;
    float wa = wt[((ocg * 8 + pr)     * CIN + ci) * 9 + kk];
    float wb = wt[((ocg * 8 + pr + 4) * CIN + ci) * 9 + kk];
    dst[i] = pack2(wa, wb);
}

// ============================================================================
// Direct 3x3 conv, FFMA2 oc-pair packing + cp.async double-buffered pipeline.
// 256 thr -> 16x64 px tile, 8 oc per blockIdx.z, 4 px/thread.
// dyn smem: in 2*8*18*68*4 = 78336 B, w 2*288*8 = 4608 B -> 82944 B
// ============================================================================
#define SIN_ELEMS (8*18*68)
#define SMEM_W_OFF (2*SIN_ELEMS*4)

template<int CIN, bool RELU>
__global__ void __launch_bounds__(256, 2) conv3x3_kernel(
    const float* __restrict__ in,   // [CIN][192][192]
    const u64*   __restrict__ pw,   // packed weights
    const float* __restrict__ bs,
    float* __restrict__ out)
{
    extern __shared__ char dsm[];
    float* s_in = (float*)dsm;                    // [2][8][18][68]
    u64*   s_w  = (u64*)(dsm + SMEM_W_OFF);       // [2][288]  (cc*4+pr)*9+kk

    const int tid  = threadIdx.x;
    const int tx   = tid & 15;
    const int ty   = tid >> 4;
    const int lane = tid & 31;
    const int wid  = tid >> 5;
    const int bw   = blockIdx.x * 64;
    const int bh   = blockIdx.y * 16;
    const int bz   = blockIdx.z;          // ocg
    const int ocg0 = bz * 8;
    const int NC   = CIN / 8;

    unsigned sin_addr = (unsigned)__cvta_generic_to_shared(s_in);
    unsigned sw_addr  = (unsigned)__cvta_generic_to_shared(s_w);

    // ---- prefetch lambda ----
    auto prefetch = [&](int chunk, int buf) {
        int ci0 = chunk * 8;
        // input tile: warp per row, 66 cols, zero-filled borders
        unsigned dbase = sin_addr + buf * (SIN_ELEMS * 4);
        const float* ibase = in + (size_t)ci0 * HW;
        for (int row = wid; row < 144; row += 8) {
            int cc = row / 18;
            int r  = row - cc * 18;
            int gy = bh - 1 + r;
            bool yok = (unsigned)gy < (unsigned)HH;
            int gyc = min(max(gy, 0), HH - 1);
            const float* src = ibase + (size_t)cc * HW + gyc * WW;
            unsigned drow = dbase + ((cc * 18 + r) * 68) * 4;
            #pragma unroll
            for (int s = 0; s < 3; s++) {
                int c0 = lane + s * 32;
                if (c0 < 66) {
                    int gx = bw - 1 + c0;
                    bool ok = yok && (unsigned)gx < (unsigned)WW;
                    int gxc = min(max(gx, 0), WW - 1);
                    cp4(drow + c0 * 4, src + gxc, ok);
                }
            }
        }
        // weights: contiguous 288 u64 = 144 x 16B
        const u64* wsrc = pw + (size_t)(bz * CIN + ci0) * 36;
        unsigned wdst = sw_addr + buf * (288 * 8);
        if (tid < 144) cp16(wdst + tid * 16, wsrc + tid * 2);
    };

    u64 acc[4][4];
    #pragma unroll
    for (int p = 0; p < 4; p++)
        #pragma unroll
        for (int q = 0; q < 4; q++) acc[p][q] = 0ull;

    prefetch(0, 0);
    cp_commit();

    for (int c = 0; c < NC; c++) {
        if (c + 1 < NC) {
            prefetch(c + 1, (c + 1) & 1);
            cp_commit();
            cp_wait<1>();
        } else {
            cp_wait<0>();
        }
        __syncthreads();

        const int buf = c & 1;
        const float* sin = s_in + buf * SIN_ELEMS;
        const u64*   sw  = s_w  + buf * 288;

        #pragma unroll
        for (int cc = 0; cc < 8; cc++) {
            #pragma unroll
            for (int kh = 0; kh < 3; kh++) {
                const float* rp = sin + ((cc * 18) + ty + kh) * 68 + tx * 4;
                float4 a = *(const float4*)rp;
                float2 b = *(const float2*)(rp + 4);
                u64 d[6];
                d[0] = pack2(a.x, a.x);
                d[1] = pack2(a.y, a.y);
                d[2] = pack2(a.z, a.z);
                d[3] = pack2(a.w, a.w);
                d[4] = pack2(b.x, b.x);
                d[5] = pack2(b.y, b.y);
                #pragma unroll
                for (int pr = 0; pr < 4; pr++) {
                    u64 w0 = sw[(cc * 4 + pr) * 9 + kh * 3 + 0];
                    u64 w1 = sw[(cc * 4 + pr) * 9 + kh * 3 + 1];
                    u64 w2 = sw[(cc * 4 + pr) * 9 + kh * 3 + 2];
                    #pragma unroll
                    for (int px = 0; px < 4; px++) {
                        acc[pr][px] = fma2(w0, d[px],     acc[pr][px]);
                        acc[pr][px] = fma2(w1, d[px + 1], acc[pr][px]);
                        acc[pr][px] = fma2(w2, d[px + 2], acc[pr][px]);
                    }
                }
            }
        }
        __syncthreads();
    }

    const size_t obase = (size_t)(bh + ty) * WW + bw + tx * 4;
    #pragma unroll
    for (int pr = 0; pr < 4; pr++) {
        float bva = bs[ocg0 + pr];
        float bvb = bs[ocg0 + pr + 4];
        float ra[4], rb[4];
        #pragma unroll
        for (int px = 0; px < 4; px++) {
            float2 f = unpack2(acc[pr][px]);
            float va = f.x + bva;
            float vb = f.y + bvb;
            if (RELU) {
                va = (va >= 0.f) ? va : 0.1f * va;
                vb = (vb >= 0.f) ? vb : 0.1f * vb;
            }
            ra[px] = va; rb[px] = vb;
        }
        *(float4*)&out[(size_t)(ocg0 + pr)     * HW + obase] =
            make_float4(ra[0], ra[1], ra[2], ra[3]);
        *(float4*)&out[(size_t)(ocg0 + pr + 4) * HW + obase] =
            make_float4(rb[0], rb[1], rb[2], rb[3]);
    }
}

#define CONV_SMEM (2*SIN_ELEMS*4 + 2*288*8)

// ============================================================================
// Transpose x: [128][HW] -> [HW][128].
// ============================================================================
__global__ void __launch_bounds__(256) transpose_kernel(
    const float* __restrict__ x, float* __restrict__ xT)
{
    __shared__ float s[32][33];
    int p0 = blockIdx.x * 32;
    int c0 = blockIdx.y * 32;
    int tx = threadIdx.x & 31;
    int ty = threadIdx.x >> 5;
    #pragma unroll
    for (int i = 0; i < 32; i += 8)
        s[ty + i][tx] = x[(size_t)(c0 + ty + i) * HW + p0 + tx];
    __syncthreads();
    #pragma unroll
    for (int i = 0; i < 32; i += 8)
        xT[(size_t)(p0 + ty + i) * 128 + c0 + tx] = s[tx][ty + i];
}

// ============================================================================
// Fused deformable conv (unchanged — R4/R5 version).
// ============================================================================
#define DPX 32
__global__ void __launch_bounds__(256) deform_kernel(
    const float* __restrict__ xT,
    const float* __restrict__ out4,
    const float* __restrict__ wt,
    const float* __restrict__ bs,
    float* __restrict__ out)
{
    __shared__ float val_s[72 * DPX];
    __shared__ float w_s[64 * 73];

    const int tid = threadIdx.x;
    const int pbase = blockIdx.x * DPX;
    const int o  = tid & 31;
    const int ps = tid >> 5;

    u64 acc[2][2];
    acc[0][0] = acc[0][1] = acc[1][0] = acc[1][1] = 0ull;

    for (int g = 0; g < 16; g++) {
        __syncthreads();
        for (int li = tid; li < 4608; li += 256) {
            int oo = li / 72;
            int j  = li - oo * 72;
            w_s[oo * 73 + j] = wt[oo * 1152 + g * 72 + j];
        }
        for (int t = tid; t < 9 * DPX; t += 256) {
            int pix = t & (DPX - 1);
            int k   = t >> 5;
            int p   = pbase + pix;
            int ho  = p / WW;
            int wo  = p - ho * WW;

            float offy = 5.f * tanhf(out4[(g * 18 + k * 2)     * HW + p]);
            float offx = 5.f * tanhf(out4[(g * 18 + k * 2 + 1) * HW + p]);
            float mz   = out4[(288 + g * 9 + k) * HW + p];
            float mv   = 1.f / (1.f + expf(-mz));

            float py = (float)(ho - 1 + k / 3) + offy;
            float px = (float)(wo - 1 + k % 3) + offx;
            float y0 = floorf(py), x0 = floorf(px);
            float wy1 = py - y0, wx1 = px - x0;

            u64 v2[4] = {0ull, 0ull, 0ull, 0ull};

            auto corner = [&](float yf, float xf, float wc) {
                if (yf >= 0.f && yf <= (float)(HH - 1) &&
                    xf >= 0.f && xf <= (float)(WW - 1)) {
                    int iy = (int)yf, ix = (int)xf;
                    const ulonglong2* q =
                        (const ulonglong2*)(xT + ((size_t)(iy * WW + ix) << 7) + (g << 3));
                    ulonglong2 q0 = q[0], q1 = q[1];
                    u64 wc2 = pack2(wc, wc);
                    v2[0] = fma2(wc2, q0.x, v2[0]);
                    v2[1] = fma2(wc2, q0.y, v2[1]);
                    v2[2] = fma2(wc2, q1.x, v2[2]);
                    v2[3] = fma2(wc2, q1.y, v2[3]);
                }
            };
            corner(y0,       x0,       (1.f - wy1) * (1.f - wx1));
            corner(y0,       x0 + 1.f, (1.f - wy1) * wx1);
            corner(y0 + 1.f, x0,       wy1 * (1.f - wx1));
            corner(y0 + 1.f, x0 + 1.f, wy1 * wx1);

            u64 m2 = pack2(mv, mv);
            #pragma unroll
            for (int c2 = 0; c2 < 4; c2++) {
                float2 ff = unpack2(mul2(v2[c2], m2));
                val_s[((c2 * 2)     * 9 + k) * DPX + pix] = ff.x;
                val_s[((c2 * 2 + 1) * 9 + k) * DPX + pix] = ff.y;
            }
        }
        __syncthreads();

        const float* wr0 = &w_s[o * 73];
        const float* wr1 = &w_s[(o + 32) * 73];
        const float* vb  = &val_s[ps * 4];
        #pragma unroll 4
        for (int j = 0; j < 72; j++) {
            float w0 = wr0[j], w1 = wr1[j];
            u64 w02 = pack2(w0, w0);
            u64 w12 = pack2(w1, w1);
            const u64* vp = (const u64*)(vb + j * DPX);
            u64 v0 = vp[0], v1 = vp[1];
            acc[0][0] = fma2(w02, v0, acc[0][0]);
            acc[0][1] = fma2(w02, v1, acc[0][1]);
            acc[1][0] = fma2(w12, v0, acc[1][0]);
            acc[1][1] = fma2(w12, v1, acc[1][1]);
        }
    }

    float bv0 = bs[o], bv1 = bs[o + 32];
    float2 a0 = unpack2(acc[0][0]), a1 = unpack2(acc[0][1]);
    float2 b0 = unpack2(acc[1][0]), b1 = unpack2(acc[1][1]);
    *(float4*)&out[(size_t)o        * HW + pbase + ps * 4] =
        make_float4(a0.x + bv0, a0.y + bv0, a1.x + bv0, a1.y + bv0);
    *(float4*)&out[(size_t)(o + 32) * HW + pbase + ps * 4] =
        make_float4(b0.x + bv1, b0.y + bv1, b1.x + bv1, b1.y + bv1);
}

// ============================================================================
// launch
// ============================================================================
extern "C" void kernel_launch(void* const* d_in, const int* in_sizes, int n_in,
                              void* d_out, int out_size)
{
    const float* x      = (const float*)d_in[0];
    const float* cond   = (const float*)d_in[1];
    const float* weight = (const float*)d_in[2];
    const float* bias   = (const float*)d_in[3];
    const float* w1     = (const float*)d_in[4];
    const float* b1     = (const float*)d_in[5];
    const float* w2     = (const float*)d_in[6];
    const float* b2     = (const float*)d_in[7];
    const float* w3     = (const float*)d_in[8];
    const float* b3     = (const float*)d_in[9];
    const float* w4     = (const float*)d_in[10];
    const float* b4     = (const float*)d_in[11];
    float* out = (float*)d_out;

    float *h1, *h2, *o4, *xT;
    u64 *pw1, *pw2, *pw3, *pw4;
    cudaGetSymbolAddress((void**)&h1, g_h1);
    cudaGetSymbolAddress((void**)&h2, g_h2);
    cudaGetSymbolAddress((void**)&o4, g_out4);
    cudaGetSymbolAddress((void**)&xT, g_xT);
    cudaGetSymbolAddress((void**)&pw1, g_pw1);
    cudaGetSymbolAddress((void**)&pw2, g_pw2);
    cudaGetSymbolAddress((void**)&pw3, g_pw3);
    cudaGetSymbolAddress((void**)&pw4, g_pw4);

    // one-time-per-launch weight prepack (cheap)
    prepack_kernel<<<(8  * 192 * 36 + 255) / 256, 256>>>(w1, 192, 8,  pw1);
    prepack_kernel<<<(8  *  64 * 36 + 255) / 256, 256>>>(w2,  64, 8,  pw2);
    prepack_kernel<<<(8  *  64 * 36 + 255) / 256, 256>>>(w3,  64, 8,  pw3);
    prepack_kernel<<<(54 *  64 * 36 + 255) / 256, 256>>>(w4,  64, 54, pw4);

    cudaFuncSetAttribute(conv3x3_kernel<192, true>,
                         cudaFuncAttributeMaxDynamicSharedMemorySize, CONV_SMEM);
    cudaFuncSetAttribute(conv3x3_kernel<64, true>,
                         cudaFuncAttributeMaxDynamicSharedMemorySize, CONV_SMEM);
    cudaFuncSetAttribute(conv3x3_kernel<64, false>,
                         cudaFuncAttributeMaxDynamicSharedMemorySize, CONV_SMEM);

    dim3 cgrid(3, 12, 8);
    conv3x3_kernel<192, true ><<<cgrid, 256, CONV_SMEM>>>(cond, pw1, b1, h1);
    conv3x3_kernel< 64, true ><<<cgrid, 256, CONV_SMEM>>>(h1,   pw2, b2, h2);
    conv3x3_kernel< 64, true ><<<cgrid, 256, CONV_SMEM>>>(h2,   pw3, b3, h1);
    dim3 cgrid4(3, 12, 54);
    conv3x3_kernel< 64, false><<<cgrid4, 256, CONV_SMEM>>>(h1,  pw4, b4, o4);

    transpose_kernel<<<dim3(1152, 4), 256>>>(x, xT);

    deform_kernel<<<HW / DPX, 256>>>(xT, o4, weight, bias, out);
}